// round 6
// baseline (speedup 1.0000x reference)
#include <cuda_runtime.h>
#include <cuda_bf16.h>

#define NN 100000
#define EMAX 6400000
#define F 32
#define SCAN_B 512
#define NBLK ((NN + SCAN_B - 1) / SCAN_B)   // 196

// Scratch (device globals)
__device__ int   g_cnt[NN];        // per-dst edge count (degree - 1)
__device__ int   g_row[NN];        // CSR row_start (exclusive scan of cnt)
__device__ int   g_off[NN];        // scatter cursor
__device__ int   g_bsum[NBLK];     // scan block sums
__device__ int   g_boff[NBLK];     // scan block offsets
__device__ int   g_csr[EMAX];      // src indices grouped by dst
__device__ float g_dis[NN];        // deg^{-1/2}
__device__ float4 g_x4[NN];        // dis * x, padded
__device__ float g_h1s[NN * F];    // dis * relu(l1)  (f32)
__device__ __nv_bfloat16 g_h1b[NN * F];  // same, bf16 (gather payload)
__device__ float g_ys[NN];         // dis * (h2 @ W3)

// ---------------------------------------------------------------------------
__global__ void zero_cnt() {
    int i = blockIdx.x * blockDim.x + threadIdx.x;
    if (i < NN) g_cnt[i] = 0;
}

__global__ void hist_kernel(const int* __restrict__ dst, int E) {
    int e = blockIdx.x * blockDim.x + threadIdx.x;
    if (e < E) atomicAdd(&g_cnt[dst[e]], 1);
}

// Block-level inclusive scan of g_cnt -> g_row (inclusive), block totals -> g_bsum
__global__ void scan1_kernel() {
    __shared__ int s[SCAN_B];
    int t = threadIdx.x;
    int i = blockIdx.x * SCAN_B + t;
    int v = (i < NN) ? g_cnt[i] : 0;
    s[t] = v;
    __syncthreads();
#pragma unroll
    for (int o = 1; o < SCAN_B; o <<= 1) {
        int add = (t >= o) ? s[t - o] : 0;
        __syncthreads();
        s[t] += add;
        __syncthreads();
    }
    if (i < NN) g_row[i] = s[t];              // inclusive for now
    if (t == SCAN_B - 1) g_bsum[blockIdx.x] = s[t];
}

// Exclusive scan of block sums (tiny, serial in smem)
__global__ void scan2_kernel() {
    __shared__ int sb[NBLK];
    int t = threadIdx.x;
    for (int i = t; i < NBLK; i += blockDim.x) sb[i] = g_bsum[i];
    __syncthreads();
    if (t == 0) {
        int run = 0;
        for (int i = 0; i < NBLK; i++) { int tmp = sb[i]; sb[i] = run; run += tmp; }
    }
    __syncthreads();
    for (int i = t; i < NBLK; i += blockDim.x) g_boff[i] = sb[i];
}

// Finalize row_start (exclusive), init scatter cursor, compute dis + pre-scaled x
__global__ void scan3_kernel(const float* __restrict__ x) {
    int i = blockIdx.x * blockDim.x + threadIdx.x;
    if (i >= NN) return;
    int cnt = g_cnt[i];
    int row = g_row[i] - cnt + g_boff[i / SCAN_B];
    g_row[i] = row;
    g_off[i] = row;
    float dis = rsqrtf((float)(cnt + 1));     // +1 = self loop
    g_dis[i] = dis;
    float4 v;
    v.x = dis * __ldg(&x[i * 3 + 0]);
    v.y = dis * __ldg(&x[i * 3 + 1]);
    v.z = dis * __ldg(&x[i * 3 + 2]);
    v.w = 0.0f;
    g_x4[i] = v;
}

__global__ void csr_scatter(const int* __restrict__ src, const int* __restrict__ dst, int E) {
    int e = blockIdx.x * blockDim.x + threadIdx.x;
    if (e >= E) return;
    int d = __ldg(&dst[e]);
    int pos = atomicAdd(&g_off[d], 1);
    g_csr[pos] = __ldg(&src[e]);
}

// ---------------------------------------------------------------------------
// Layer 1 (fused agg + node): warp per node. Gather x4 over neighbors,
// warp-reduce, then each lane emits one of 32 output features.
__global__ void l1_kernel(const float* __restrict__ W1, const float* __restrict__ b1) {
    int gw = (blockIdx.x * blockDim.x + threadIdx.x) >> 5;
    int lane = threadIdx.x & 31;
    if (gw >= NN) return;
    int n = gw;
    int base = g_row[n];
    int cnt = g_cnt[n];
    float ax = 0.f, ay = 0.f, az = 0.f;
    for (int j0 = 0; j0 < cnt; j0 += 32) {
        int j = j0 + lane;
        if (j < cnt) {
            int s = __ldg(&g_csr[base + j]);
            float4 v = __ldg(&g_x4[s]);
            ax += v.x; ay += v.y; az += v.z;
        }
    }
#pragma unroll
    for (int o = 16; o > 0; o >>= 1) {
        ax += __shfl_xor_sync(0xFFFFFFFFu, ax, o);
        ay += __shfl_xor_sync(0xFFFFFFFFu, ay, o);
        az += __shfl_xor_sync(0xFFFFFFFFu, az, o);
    }
    float dis = g_dis[n];
    float4 xs = g_x4[n];                       // self message (already dis-scaled)
    float a0 = dis * (ax + xs.x);
    float a1 = dis * (ay + xs.y);
    float a2 = dis * (az + xs.z);
    float o = dis * fmaxf(0.0f, __ldg(&b1[lane])
                  + a0 * __ldg(&W1[0 * F + lane])
                  + a1 * __ldg(&W1[1 * F + lane])
                  + a2 * __ldg(&W1[2 * F + lane]));
    g_h1s[n * F + lane] = o;
    g_h1b[n * F + lane] = __float2bfloat16(o);
}

// ---------------------------------------------------------------------------
// Layer 2+3 (fused agg + W2 matmul + relu + W3 dot): warp per node, lane = feature.
__global__ void l2l3_kernel(const float* __restrict__ W2, const float* __restrict__ b2,
                            const float* __restrict__ W3) {
    __shared__ float sW2[F * F];
    __shared__ float sb2[F];
    __shared__ float sW3[F];
    for (int i = threadIdx.x; i < F * F; i += blockDim.x) sW2[i] = __ldg(&W2[i]);
    if (threadIdx.x < F) { sb2[threadIdx.x] = __ldg(&b2[threadIdx.x]); sW3[threadIdx.x] = __ldg(&W3[threadIdx.x]); }
    __syncthreads();

    int gw = (blockIdx.x * blockDim.x + threadIdx.x) >> 5;
    int lane = threadIdx.x & 31;
    if (gw >= NN) return;
    int n = gw;
    int base = g_row[n];
    int cnt = g_cnt[n];

    float acc0 = 0.f, acc1 = 0.f;
    for (int j0 = 0; j0 < cnt; j0 += 32) {
        int m = min(32, cnt - j0);
        int idx = 0;
        if (lane < m) idx = __ldg(&g_csr[base + j0 + lane]);
        int j = 0;
        for (; j + 1 < m; j += 2) {
            int s0 = __shfl_sync(0xFFFFFFFFu, idx, j);
            int s1 = __shfl_sync(0xFFFFFFFFu, idx, j + 1);
            float v0 = __bfloat162float(__ldg(&g_h1b[s0 * F + lane]));
            float v1 = __bfloat162float(__ldg(&g_h1b[s1 * F + lane]));
            acc0 += v0; acc1 += v1;
        }
        if (j < m) {
            int s0 = __shfl_sync(0xFFFFFFFFu, idx, j);
            acc0 += __bfloat162float(__ldg(&g_h1b[s0 * F + lane]));
        }
    }
    float dis = g_dis[n];
    float inv = dis * (acc0 + acc1 + g_h1s[n * F + lane]);   // self term in f32

    float r = sb2[lane];
#pragma unroll
    for (int k = 0; k < F; k++) {
        float hv = __shfl_sync(0xFFFFFFFFu, inv, k);
        r += hv * sW2[k * F + lane];
    }
    float h2 = fmaxf(0.0f, r);
    float part = h2 * sW3[lane];
#pragma unroll
    for (int o = 16; o > 0; o >>= 1)
        part += __shfl_xor_sync(0xFFFFFFFFu, part, o);
    if (lane == 0) g_ys[n] = dis * part;
}

// ---------------------------------------------------------------------------
// Layer 3 (fused agg + finalize): warp per node, scalar gathers of g_ys.
__global__ void l3_kernel(const float* __restrict__ b3, float* __restrict__ out) {
    int gw = (blockIdx.x * blockDim.x + threadIdx.x) >> 5;
    int lane = threadIdx.x & 31;
    if (gw >= NN) return;
    int n = gw;
    int base = g_row[n];
    int cnt = g_cnt[n];
    float a = 0.f;
    for (int j = lane; j < cnt; j += 32) {
        int s = __ldg(&g_csr[base + j]);
        a += __ldg(&g_ys[s]);
    }
#pragma unroll
    for (int o = 16; o > 0; o >>= 1)
        a += __shfl_xor_sync(0xFFFFFFFFu, a, o);
    if (lane == 0)
        out[n] = __ldg(&b3[0]) + g_dis[n] * (a + g_ys[n]);
}

// ---------------------------------------------------------------------------
extern "C" void kernel_launch(void* const* d_in, const int* in_sizes, int n_in,
                              void* d_out, int out_size) {
    const float* x  = (const float*)d_in[0];
    const int*   ei = (const int*)d_in[1];
    const float* W1 = (const float*)d_in[2];
    const float* b1 = (const float*)d_in[3];
    const float* W2 = (const float*)d_in[4];
    const float* b2 = (const float*)d_in[5];
    const float* W3 = (const float*)d_in[6];
    const float* b3 = (const float*)d_in[7];
    float* out = (float*)d_out;

    int E = in_sizes[1] / 2;
    const int* src = ei;
    const int* dst = ei + E;

    const int B = 256;
    zero_cnt<<<(NN + B - 1) / B, B>>>();
    hist_kernel<<<(E + B - 1) / B, B>>>(dst, E);
    scan1_kernel<<<NBLK, SCAN_B>>>();
    scan2_kernel<<<1, 256>>>();
    scan3_kernel<<<(NN + B - 1) / B, B>>>(x);
    csr_scatter<<<(E + B - 1) / B, B>>>(src, dst, E);

    int warpGrid = (NN * 32 + B - 1) / B;
    l1_kernel<<<warpGrid, B>>>(W1, b1);
    l2l3_kernel<<<warpGrid, B>>>(W2, b2, W3);
    l3_kernel<<<warpGrid, B>>>(b3, out);
}

// round 10
// speedup vs baseline: 1.2654x; 1.2654x over previous
#include <cuda_runtime.h>
#include <cuda_bf16.h>

#define NN 100000
#define F 32

// Scratch (device globals)
__device__ float g_deg[NN];               // degree (starts at 1 for self loop)
__device__ float g_dis[NN];               // deg^{-1/2}
__device__ float4 g_x4[NN];               // dis * x, padded to 4 (w=0)
__device__ float4 g_agg1[NN];             // layer-1 edge aggregation
__device__ float g_h1s[NN * F];           // dis * relu(l1)  (f32, self-term reads)
__device__ __nv_bfloat16 g_h1b[NN * F];   // same in bf16 (edge gather payload)
__device__ float g_agg2[NN * F];          // layer-2 edge aggregation (f32)
__device__ float g_ys[NN];                // dis * (h2 @ W3)
__device__ float g_acc3[NN];              // layer-3 edge aggregation

// ---------------------------------------------------------------------------
// Fused: zero all aggregation buffers + degree histogram (independent work)
__global__ void init_deg_kernel(const int* __restrict__ dst, int E) {
    int i = blockIdx.x * blockDim.x + threadIdx.x;
    if (i < NN * F) g_agg2[i] = 0.0f;
    if (i < NN) {
        g_agg1[i] = make_float4(0.f, 0.f, 0.f, 0.f);
        g_acc3[i] = 0.0f;
        g_deg[i] = 1.0f;   // self loop
    }
}

__global__ void deg_kernel(const int* __restrict__ dst, int E) {
    int e = blockIdx.x * blockDim.x + threadIdx.x;
    if (e < E) atomicAdd(&g_deg[dst[e]], 1.0f);
}

// dis = rsqrt(deg); pre-scale x by dis (pad to float4)
__global__ void pre1_kernel(const float* __restrict__ x) {
    int n = blockIdx.x * blockDim.x + threadIdx.x;
    if (n >= NN) return;
    float dis = rsqrtf(g_deg[n]);
    g_dis[n] = dis;
    float4 v;
    v.x = dis * __ldg(&x[n * 3 + 0]);
    v.y = dis * __ldg(&x[n * 3 + 1]);
    v.z = dis * __ldg(&x[n * 3 + 2]);
    v.w = 0.0f;
    g_x4[n] = v;
}

// ---------------------------------------------------------------------------
// Layer 1 edge pass: pure gather + vector RED (features pre-scaled by dis[src])
__global__ void l1_edge(const int* __restrict__ src, const int* __restrict__ dst, int E) {
    int e = blockIdx.x * blockDim.x + threadIdx.x;
    if (e >= E) return;
    int s = __ldg(&src[e]);
    int d = __ldg(&dst[e]);
    float4 v = __ldg(&g_x4[s]);
    float* p = reinterpret_cast<float*>(&g_agg1[d]);
    asm volatile("red.global.add.v4.f32 [%0], {%1, %2, %3, %4};"
                 :: "l"(p), "f"(v.x), "f"(v.y), "f"(v.z), "f"(v.w) : "memory");
}

// Layer 1 node pass: A = dis*(agg1 + x4_self); h1 = relu(A@W1+b1); store dis*h1
// as f32 (self reads) and bf16 (edge gather payload). 8 threads per node.
__global__ void l1_node(const float* __restrict__ W1, const float* __restrict__ b1) {
    int t = blockIdx.x * blockDim.x + threadIdx.x;
    if (t >= NN * 8) return;
    int n = t >> 3;
    int c = t & 7;
    float dis = g_dis[n];
    float4 a = g_agg1[n];
    float4 xs = g_x4[n];             // self message (already dis-scaled)
    float a0 = dis * (a.x + xs.x);
    float a1 = dis * (a.y + xs.y);
    float a2 = dis * (a.z + xs.z);
    int f0 = c * 4;
    float4 o;
    o.x = dis * fmaxf(0.0f, __ldg(&b1[f0 + 0]) + a0 * __ldg(&W1[0 * F + f0 + 0]) + a1 * __ldg(&W1[1 * F + f0 + 0]) + a2 * __ldg(&W1[2 * F + f0 + 0]));
    o.y = dis * fmaxf(0.0f, __ldg(&b1[f0 + 1]) + a0 * __ldg(&W1[0 * F + f0 + 1]) + a1 * __ldg(&W1[1 * F + f0 + 1]) + a2 * __ldg(&W1[2 * F + f0 + 1]));
    o.z = dis * fmaxf(0.0f, __ldg(&b1[f0 + 2]) + a0 * __ldg(&W1[0 * F + f0 + 2]) + a1 * __ldg(&W1[1 * F + f0 + 2]) + a2 * __ldg(&W1[2 * F + f0 + 2]));
    o.w = dis * fmaxf(0.0f, __ldg(&b1[f0 + 3]) + a0 * __ldg(&W1[0 * F + f0 + 3]) + a1 * __ldg(&W1[1 * F + f0 + 3]) + a2 * __ldg(&W1[2 * F + f0 + 3]));
    *reinterpret_cast<float4*>(&g_h1s[n * F + f0]) = o;

    __nv_bfloat162 p0 = __floats2bfloat162_rn(o.x, o.y);
    __nv_bfloat162 p1 = __floats2bfloat162_rn(o.z, o.w);
    uint2 packed;
    packed.x = *reinterpret_cast<unsigned int*>(&p0);
    packed.y = *reinterpret_cast<unsigned int*>(&p1);
    *reinterpret_cast<uint2*>(&g_h1b[n * F + f0]) = packed;
}

// ---------------------------------------------------------------------------
// Layer 2 edge pass: 8 lanes per edge, lane c gathers bf16x4 chunk (8B) of the
// source row — 2 sectors/edge instead of 4 — then f32 v4 RED to agg2[dst].
__global__ void l2_edge(const int* __restrict__ src, const int* __restrict__ dst, int E) {
    long long t = (long long)blockIdx.x * blockDim.x + threadIdx.x;
    if (t >= (long long)E * 8) return;
    int e = (int)(t >> 3);
    int c = (int)(t & 7);
    int s = __ldg(&src[e]);
    int d = __ldg(&dst[e]);
    uint2 packed = __ldg(reinterpret_cast<const uint2*>(&g_h1b[s * F + c * 4]));
    __nv_bfloat162 p0 = *reinterpret_cast<__nv_bfloat162*>(&packed.x);
    __nv_bfloat162 p1 = *reinterpret_cast<__nv_bfloat162*>(&packed.y);
    float2 f0 = __bfloat1622float2(p0);
    float2 f1 = __bfloat1622float2(p1);
    float* p = &g_agg2[d * F + c * 4];
    asm volatile("red.global.add.v4.f32 [%0], {%1, %2, %3, %4};"
                 :: "l"(p), "f"(f0.x), "f"(f0.y), "f"(f1.x), "f"(f1.y) : "memory");
}

// Layer 2+3 node pass (one warp per node, lane = feature):
//   in = dis*(agg2 + h1s_self); h2 = relu(in@W2+b2); ys = dis*(h2 @ W3)
__global__ void l2l3_node(const float* __restrict__ W2, const float* __restrict__ b2,
                          const float* __restrict__ W3) {
    __shared__ float sW2[F * F];
    __shared__ float sb2[F];
    __shared__ float sW3[F];
    for (int i = threadIdx.x; i < F * F; i += blockDim.x) sW2[i] = __ldg(&W2[i]);
    if (threadIdx.x < F) { sb2[threadIdx.x] = __ldg(&b2[threadIdx.x]); sW3[threadIdx.x] = __ldg(&W3[threadIdx.x]); }
    __syncthreads();

    int gw = (blockIdx.x * blockDim.x + threadIdx.x) >> 5;
    int lane = threadIdx.x & 31;
    if (gw >= NN) return;
    int n = gw;
    float dis = g_dis[n];
    float inv = dis * (g_agg2[n * F + lane] + g_h1s[n * F + lane]);
    float acc = sb2[lane];
#pragma unroll
    for (int k = 0; k < F; k++) {
        float hv = __shfl_sync(0xFFFFFFFFu, inv, k);
        acc += hv * sW2[k * F + lane];
    }
    float h2 = fmaxf(0.0f, acc);
    float part = h2 * sW3[lane];
#pragma unroll
    for (int o = 16; o > 0; o >>= 1)
        part += __shfl_xor_sync(0xFFFFFFFFu, part, o);
    if (lane == 0) g_ys[n] = dis * part;
}

// Layer 3 edge pass: scalar gather + RED (no dis loads)
__global__ void l3_edge(const int* __restrict__ src, const int* __restrict__ dst, int E) {
    int e = blockIdx.x * blockDim.x + threadIdx.x;
    if (e >= E) return;
    int s = __ldg(&src[e]);
    int d = __ldg(&dst[e]);
    atomicAdd(&g_acc3[d], __ldg(&g_ys[s]));
}

// Finalize: out[n] = b3 + dis[n]*(acc3[n] + ys_self[n])
__global__ void finalize_kernel(const float* __restrict__ b3, float* __restrict__ out) {
    int n = blockIdx.x * blockDim.x + threadIdx.x;
    if (n >= NN) return;
    out[n] = __ldg(&b3[0]) + g_dis[n] * (g_acc3[n] + g_ys[n]);
}

// ---------------------------------------------------------------------------
extern "C" void kernel_launch(void* const* d_in, const int* in_sizes, int n_in,
                              void* d_out, int out_size) {
    const float* x  = (const float*)d_in[0];
    const int*   ei = (const int*)d_in[1];
    const float* W1 = (const float*)d_in[2];
    const float* b1 = (const float*)d_in[3];
    const float* W2 = (const float*)d_in[4];
    const float* b2 = (const float*)d_in[5];
    const float* W3 = (const float*)d_in[6];
    const float* b3 = (const float*)d_in[7];
    float* out = (float*)d_out;

    int E = in_sizes[1] / 2;
    const int* src = ei;
    const int* dst = ei + E;

    const int B = 256;
    init_deg_kernel<<<(NN * F + B - 1) / B, B>>>(dst, E);
    deg_kernel<<<(E + B - 1) / B, B>>>(dst, E);
    pre1_kernel<<<(NN + B - 1) / B, B>>>(x);

    l1_edge<<<(E + B - 1) / B, B>>>(src, dst, E);
    l1_node<<<(NN * 8 + B - 1) / B, B>>>(W1, b1);

    long long t2 = (long long)E * 8;
    l2_edge<<<(unsigned)((t2 + B - 1) / B), B>>>(src, dst, E);
    l2l3_node<<<(NN * 32 + B - 1) / B, B>>>(W2, b2, W3);

    l3_edge<<<(E + B - 1) / B, B>>>(src, dst, E);
    finalize_kernel<<<(NN + B - 1) / B, B>>>(b3, out);
}